// round 5
// baseline (speedup 1.0000x reference)
#include <cuda_runtime.h>

#define NMAX 100000
#define EMAX 1000000

// ---- scratch (device globals; no allocation allowed) ----
__device__ int   g_cnt[NMAX];
__device__ int   g_rowoff[NMAX + 1];
__device__ int   g_cursor[NMAX];
__device__ int   g_col[EMAX + NMAX];
__device__ float g_dinv[NMAX];
__device__ int   g_bsum[512];
__device__ float g_h[NMAX * 64];       // layer-1 activation (only intermediate left)

// ---------------- packed fp32x2 helpers ----------------

__device__ __forceinline__ unsigned long long ffma2(unsigned long long a,
                                                    unsigned long long b,
                                                    unsigned long long c) {
    unsigned long long d;
    asm("fma.rn.f32x2 %0, %1, %2, %3;" : "=l"(d) : "l"(a), "l"(b), "l"(c));
    return d;
}
__device__ __forceinline__ unsigned long long pack2(float x, float y) {
    unsigned long long r;
    asm("mov.b64 %0, {%1, %2};" : "=l"(r) : "f"(x), "f"(y));
    return r;
}
__device__ __forceinline__ float2 unpack2(unsigned long long v) {
    float2 r;
    asm("mov.b64 {%0, %1}, %2;" : "=f"(r.x), "=f"(r.y) : "l"(v));
    return r;
}

// ---------------- CSR construction ----------------

__global__ void k_count(const int* __restrict__ ei, int e) {
    int i = blockIdx.x * blockDim.x + threadIdx.x;
    if (i < e) atomicAdd(&g_cnt[ei[e + i]], 1);
}

__global__ void __launch_bounds__(256) k_scan_block(int n) {
    __shared__ int wsum[8];
    int t = threadIdx.x;
    int i = blockIdx.x * 256 + t;
    int v = (i < n) ? g_cnt[i] + 1 : 0;   // +1 = self loop
    int lane = t & 31, w = t >> 5;
    int s = v;
#pragma unroll
    for (int o = 1; o < 32; o <<= 1) {
        int a = __shfl_up_sync(0xffffffffu, s, o);
        if (lane >= o) s += a;
    }
    if (lane == 31) wsum[w] = s;
    __syncthreads();
    if (w == 0) {
        int ws = (lane < 8) ? wsum[lane] : 0;
#pragma unroll
        for (int o = 1; o < 8; o <<= 1) {
            int a = __shfl_up_sync(0xffffffffu, ws, o);
            if (lane >= o) ws += a;
        }
        if (lane < 8) wsum[lane] = ws;
    }
    __syncthreads();
    int excl = s - v + (w > 0 ? wsum[w - 1] : 0);
    if (i < n) g_rowoff[i] = excl;
    if (t == 255) g_bsum[blockIdx.x] = excl + v;
}

__global__ void __launch_bounds__(512) k_scan_bsum(int nb) {
    __shared__ int wsum[16];
    int t = threadIdx.x, lane = t & 31, w = t >> 5;
    int v = (t < nb) ? g_bsum[t] : 0;
    int s = v;
#pragma unroll
    for (int o = 1; o < 32; o <<= 1) {
        int a = __shfl_up_sync(0xffffffffu, s, o);
        if (lane >= o) s += a;
    }
    if (lane == 31) wsum[w] = s;
    __syncthreads();
    if (w == 0) {
        int ws = (lane < 16) ? wsum[lane] : 0;
#pragma unroll
        for (int o = 1; o < 16; o <<= 1) {
            int a = __shfl_up_sync(0xffffffffu, ws, o);
            if (lane >= o) ws += a;
        }
        if (lane < 16) wsum[lane] = ws;
    }
    __syncthreads();
    g_bsum[t] = s - v + (w > 0 ? wsum[w - 1] : 0);
}

__global__ void k_finalize(int n, int e) {
    int i = blockIdx.x * blockDim.x + threadIdx.x;
    if (i < n) {
        int v = g_rowoff[i] + g_bsum[i >> 8];
        g_rowoff[i] = v;
        g_cursor[i] = v;
        g_dinv[i]   = rsqrtf((float)(g_cnt[i] + 1));
    }
    if (i == 0) g_rowoff[n] = e + n;
}

__global__ void k_fill(const int* __restrict__ ei, int e, int n) {
    int i = blockIdx.x * blockDim.x + threadIdx.x;
    int src, dst;
    if (i < e) {
        src = ei[i];
        dst = ei[e + i];
    } else if (i < e + n) {
        src = dst = i - e;
    } else {
        return;
    }
    int pos = atomicAdd(&g_cursor[dst], 1);
    g_col[pos] = src;
}

// ---------------- fused GCN layer ----------------
// Per 128-row block:
//   phase 1: warp-per-row gather-aggregate  Xs[r] = dinv[r] * sum(dinv[s] * X[s])
//   phase 2: Xs @ W (+bias, relu) via fp32x2 FMA
//   FUSE_CLS: phase 2 result -> Xs, then Xs @ Wl + bl -> out (classifier fused)
// Xs swizzle: col c of row r stored at c ^ ((r>>1 & 7) << 2)  -> conflict-free
// for both the float2 agg stores and the 8-distinct-row GEMM reads.

template <bool FUSE_CLS>
__global__ void __launch_bounds__(256) k_layer(const float* __restrict__ X,
                                               const float* __restrict__ W,
                                               const float* __restrict__ bias,
                                               const float* __restrict__ Wl,
                                               const float* __restrict__ bl,
                                               float* __restrict__ Y, int n) {
    __shared__ float Xs[128 * 64];   // 32 KB
    __shared__ float Ws[64 * 64];    // 16 KB
    int t  = threadIdx.x;
    int r0 = blockIdx.x * 128;
    int lane = t & 31;
    int warp = t >> 5;

    // load W (64x64)
    for (int i = t; i < 64 * 16; i += 256)
        ((float4*)Ws)[i] = ((const float4*)W)[i];

    // ---- phase 1: aggregation, 16 rows per warp ----
    int f = lane * 2;
    for (int i = 0; i < 16; i++) {
        int r   = warp * 16 + i;
        int dst = r0 + r;
        int sw  = ((r >> 1) & 7) << 2;
        float* dstp = &Xs[r * 64 + (f ^ sw)];
        if (dst >= n) { dstp[0] = 0.f; dstp[1] = 0.f; continue; }
        int start = g_rowoff[dst];
        int end   = g_rowoff[dst + 1];
        float ax = 0.f, ay = 0.f;
        for (int base = start; base < end; base += 32) {
            int m = min(32, end - base);
            int   idx = (lane < m) ? g_col[base + lane] : 0;
            float dwl = (lane < m) ? g_dinv[idx] : 0.f;
            for (int u = 0; u < m; u++) {
                int   s = __shfl_sync(0xffffffffu, idx, u);
                float w = __shfl_sync(0xffffffffu, dwl, u);
                float2 v = *(const float2*)&X[(size_t)s * 64 + f];
                ax = fmaf(w, v.x, ax);
                ay = fmaf(w, v.y, ay);
            }
        }
        float d = g_dinv[dst];
        dstp[0] = d * ax;
        dstp[1] = d * ay;
    }
    __syncthreads();

    // ---- phase 2: GEMM 128x64 @ 64x64, 2 rows x 16 cols per thread ----
    int cg = t & 3, tr = t >> 2;
    int c0 = cg * 16;
    int sw = (tr & 7) << 2;          // == ((r>>1)&7)<<2 for r = 2*tr+rr

    unsigned long long acc[2][8];
#pragma unroll
    for (int rr = 0; rr < 2; rr++)
#pragma unroll
        for (int j = 0; j < 8; j++) acc[rr][j] = 0ull;

#pragma unroll
    for (int k = 0; k < 64; k++) {
        const ulonglong2* wp = (const ulonglong2*)&Ws[k * 64 + c0];
        ulonglong2 w0 = wp[0], w1 = wp[1], w2 = wp[2], w3 = wp[3];
        float xv0 = Xs[(tr * 2 + 0) * 64 + (k ^ sw)];
        float xv1 = Xs[(tr * 2 + 1) * 64 + (k ^ sw)];
        unsigned long long xx0 = pack2(xv0, xv0);
        unsigned long long xx1 = pack2(xv1, xv1);
        acc[0][0] = ffma2(xx0, w0.x, acc[0][0]);
        acc[0][1] = ffma2(xx0, w0.y, acc[0][1]);
        acc[0][2] = ffma2(xx0, w1.x, acc[0][2]);
        acc[0][3] = ffma2(xx0, w1.y, acc[0][3]);
        acc[0][4] = ffma2(xx0, w2.x, acc[0][4]);
        acc[0][5] = ffma2(xx0, w2.y, acc[0][5]);
        acc[0][6] = ffma2(xx0, w3.x, acc[0][6]);
        acc[0][7] = ffma2(xx0, w3.y, acc[0][7]);
        acc[1][0] = ffma2(xx1, w0.x, acc[1][0]);
        acc[1][1] = ffma2(xx1, w0.y, acc[1][1]);
        acc[1][2] = ffma2(xx1, w1.x, acc[1][2]);
        acc[1][3] = ffma2(xx1, w1.y, acc[1][3]);
        acc[1][4] = ffma2(xx1, w2.x, acc[1][4]);
        acc[1][5] = ffma2(xx1, w2.y, acc[1][5]);
        acc[1][6] = ffma2(xx1, w3.x, acc[1][6]);
        acc[1][7] = ffma2(xx1, w3.y, acc[1][7]);
    }

    // bias + relu
    float hv[2][16];
#pragma unroll
    for (int rr = 0; rr < 2; rr++)
#pragma unroll
        for (int j = 0; j < 8; j++) {
            float2 p = unpack2(acc[rr][j]);
            hv[rr][2 * j]     = fmaxf(p.x + bias[c0 + 2 * j], 0.f);
            hv[rr][2 * j + 1] = fmaxf(p.y + bias[c0 + 2 * j + 1], 0.f);
        }

    if (!FUSE_CLS) {
        // write h1
#pragma unroll
        for (int rr = 0; rr < 2; rr++) {
            int r = r0 + tr * 2 + rr;
            if (r < n) {
#pragma unroll
                for (int j = 0; j < 16; j += 4)
                    *(float4*)&Y[(size_t)r * 64 + c0 + j] =
                        *(float4*)&hv[rr][j];
            }
        }
        return;
    }

    // ---- phase 3: fused classifier ----
    __syncthreads();   // all Xs reads & Ws reads of phase 2 complete
    // h2 tile -> Xs (same swizzle); Wl -> Ws
#pragma unroll
    for (int rr = 0; rr < 2; rr++) {
        int r = tr * 2 + rr;
#pragma unroll
        for (int j = 0; j < 16; j += 4)
            *(float4*)&Xs[r * 64 + ((c0 + j) ^ sw)] = *(float4*)&hv[rr][j];
    }
    for (int i = t; i < 64 * 8; i += 256)
        ((float4*)Ws)[i] = ((const float4*)Wl)[i];
    __syncthreads();

    int c3 = (t & 3) * 8;
    unsigned long long a3[2][4];
#pragma unroll
    for (int rr = 0; rr < 2; rr++)
#pragma unroll
        for (int j = 0; j < 4; j++) a3[rr][j] = 0ull;

#pragma unroll
    for (int k = 0; k < 64; k++) {
        const ulonglong2* wp = (const ulonglong2*)&Ws[k * 32 + c3];
        ulonglong2 w0 = wp[0], w1 = wp[1];
        float xv0 = Xs[(tr * 2 + 0) * 64 + (k ^ sw)];
        float xv1 = Xs[(tr * 2 + 1) * 64 + (k ^ sw)];
        unsigned long long xx0 = pack2(xv0, xv0);
        unsigned long long xx1 = pack2(xv1, xv1);
        a3[0][0] = ffma2(xx0, w0.x, a3[0][0]);
        a3[0][1] = ffma2(xx0, w0.y, a3[0][1]);
        a3[0][2] = ffma2(xx0, w1.x, a3[0][2]);
        a3[0][3] = ffma2(xx0, w1.y, a3[0][3]);
        a3[1][0] = ffma2(xx1, w0.x, a3[1][0]);
        a3[1][1] = ffma2(xx1, w0.y, a3[1][1]);
        a3[1][2] = ffma2(xx1, w1.x, a3[1][2]);
        a3[1][3] = ffma2(xx1, w1.y, a3[1][3]);
    }

#pragma unroll
    for (int rr = 0; rr < 2; rr++) {
        int r = r0 + tr * 2 + rr;
        if (r < n) {
            float o[8];
#pragma unroll
            for (int j = 0; j < 4; j++) {
                float2 p = unpack2(a3[rr][j]);
                o[2 * j]     = p.x + bl[c3 + 2 * j];
                o[2 * j + 1] = p.y + bl[c3 + 2 * j + 1];
            }
            *(float4*)&Y[(size_t)r * 32 + c3]     = *(float4*)&o[0];
            *(float4*)&Y[(size_t)r * 32 + c3 + 4] = *(float4*)&o[4];
        }
    }
}

// ---------------- launch ----------------

extern "C" void kernel_launch(void* const* d_in, const int* in_sizes, int n_in,
                              void* d_out, int out_size) {
    const float* x  = (const float*)d_in[0];
    const int*   ei = (const int*)d_in[1];
    const float* W1 = (const float*)d_in[2];
    const float* b1 = (const float*)d_in[3];
    const float* W2 = (const float*)d_in[4];
    const float* b2 = (const float*)d_in[5];
    const float* Wl = (const float*)d_in[6];
    const float* bl = (const float*)d_in[7];
    float* out = (float*)d_out;

    int n = in_sizes[0] / 64;   // 100000
    int e = in_sizes[1] / 2;    // 1000000

    float* h_ptr = nullptr;
    int*   cnt_ptr = nullptr;
    cudaGetSymbolAddress((void**)&h_ptr, g_h);
    cudaGetSymbolAddress((void**)&cnt_ptr, g_cnt);

    int nb = (n + 255) / 256;

    // CSR + normalization build
    cudaMemsetAsync(cnt_ptr, 0, (size_t)n * sizeof(int));
    k_count<<<(e + 255) / 256, 256>>>(ei, e);
    k_scan_block<<<nb, 256>>>(n);
    k_scan_bsum<<<1, 512>>>(nb);
    k_finalize<<<nb, 256>>>(n, e);
    k_fill<<<(e + n + 255) / 256, 256>>>(ei, e, n);

    int blocks = (n + 127) / 128;

    // layer 1: h = relu((A x) W1 + b1)
    k_layer<false><<<blocks, 256>>>(x, W1, b1, nullptr, nullptr, h_ptr, n);
    // layer 2 + classifier: out = relu((A h) W2 + b2) @ Wl + bl
    k_layer<true><<<blocks, 256>>>(h_ptr, W2, b2, Wl, bl, out, n);
}